// round 6
// baseline (speedup 1.0000x reference)
#include <cuda_runtime.h>
#include <math.h>

#define BATCH   16
#define DMODEL  512
#define DSTATE  64
#define LEN     4096
#define TT      32

// ---------------- scratch (device globals: no allocations allowed) ----------
__device__ __align__(16) float g_zr[DMODEL*DSTATE];
__device__ __align__(16) float g_zi[DMODEL*DSTATE];
__device__ __align__(16) float g_wr[DMODEL*DSTATE];
__device__ __align__(16) float g_wi[DMODEL*DSTATE];
__device__ __align__(16) float g_w2r[DMODEL*DSTATE];
__device__ __align__(16) float g_w2i[DMODEL*DSTATE];
__device__ __align__(16) float g_gelu[(size_t)BATCH*DMODEL*LEN];   // 128 MB
__device__ __align__(16) float g_pooled[BATCH*DMODEL];

// ---------------- kernel 1: SSM constants (fp64 for phase accuracy) ---------
__global__ void k_params(const float* __restrict__ log_dt,
                         const float* __restrict__ log_A_real,
                         const float* __restrict__ A_imag,
                         const float* __restrict__ B_re,
                         const float* __restrict__ B_im,
                         const float* __restrict__ C_re,
                         const float* __restrict__ C_im) {
    int i = blockIdx.x * blockDim.x + threadIdx.x;
    if (i >= DMODEL * DSTATE) return;
    int d = i / DSTATE;
    double dt   = exp((double)log_dt[d]);
    double Ar   = -exp((double)log_A_real[i]);
    double Ai   = (double)A_imag[i];
    double dtAr = Ar * dt, dtAi = Ai * dt;
    double er = exp(dtAr);
    double zr = er * cos(dtAi), zi = er * sin(dtAi);
    // Bbar = (z - 1)/A * B ;  w = C * Bbar
    double den  = Ar * Ar + Ai * Ai;
    double numr = zr - 1.0, numi = zi;
    double qr = (numr * Ar + numi * Ai) / den;
    double qi = (numi * Ar - numr * Ai) / den;
    double Br = (double)B_re[i], Bi = (double)B_im[i];
    double bbr = qr * Br - qi * Bi, bbi = qr * Bi + qi * Br;
    double Cr = (double)C_re[i], Ci = (double)C_im[i];
    double wr = Cr * bbr - Ci * bbi, wi = Cr * bbi + Ci * bbr;
    // z^L  (fp64: phase up to ~8e4 rad handled exactly enough)
    double eL = exp((double)LEN * dtAr);
    double ph = (double)LEN * dtAi;
    double zLr = eL * cos(ph), zLi = eL * sin(ph);
    double w2r = -(wr * zLr - wi * zLi);
    double w2i = -(wr * zLi + wi * zLr);
    g_zr[i] = (float)zr;  g_zi[i] = (float)zi;
    g_wr[i] = (float)wr;  g_wi[i] = (float)wi;
    g_w2r[i] = (float)w2r; g_w2i[i] = (float)w2i;
}

// ---------------- kernel 2: zero pooled accumulator -------------------------
__global__ void k_zero() {
    int i = blockIdx.x * blockDim.x + threadIdx.x;
    if (i < BATCH * DMODEL) g_pooled[i] = 0.0f;
}

// ---------------- kernel 3: dual backward scan + skip + GELU ----------------
// y[x] = Re(sum_n  w z^{L-1-x} H0  -  w z^L H(x+1)),  H(t)=sum_{i>=t} u[i] z^{i-t}
__global__ __launch_bounds__(64) void k_scan(const float* __restrict__ u,
                                             const float* __restrict__ Dp) {
    __shared__ float su[TT];
    __shared__ float sbuf[DSTATE][TT + 1];
    __shared__ float pbuf[2][TT];

    int bd = blockIdx.x;                 // b*DMODEL + d
    int d  = bd & (DMODEL - 1);
    const float* ub = u + (size_t)bd * LEN;
    float* gb = g_gelu + (size_t)bd * LEN;

    int n  = threadIdx.x;
    int dn = d * DSTATE + n;
    float zr = g_zr[dn],  zi = g_zi[dn];
    float wr = g_wr[dn],  wi = g_wi[dn];
    float w2r = g_w2r[dn], w2i = g_w2i[dn];
    float Dd = Dp[d];

    // ---- pass A: H0 = sum_j u[j] z^j  (Horner from the top, stable) ----
    float Hr = 0.0f, Hi = 0.0f;
    for (int x0 = LEN - TT; x0 >= 0; x0 -= TT) {
        __syncthreads();
        if (threadIdx.x < TT) su[threadIdx.x] = ub[x0 + threadIdx.x];
        __syncthreads();
        #pragma unroll
        for (int t = TT - 1; t >= 0; --t) {
            float uu = su[t];
            float hr = fmaf(zr, Hr, fmaf(-zi, Hi, uu));
            float hi = fmaf(zi, Hr, zr * Hi);
            Hr = hr; Hi = hi;
        }
    }
    float br = fmaf(wr, Hr, -wi * Hi);   // beta(L-1) = w * H0
    float bi = fmaf(wr, Hi,  wi * Hr);

    // ---- pass B: emit y backward ----
    Hr = 0.0f; Hi = 0.0f;                // H(L) = 0
    int tred = threadIdx.x & 31;
    int nh   = threadIdx.x >> 5;
    for (int x0 = LEN - TT; x0 >= 0; x0 -= TT) {
        __syncthreads();
        if (threadIdx.x < TT) su[threadIdx.x] = ub[x0 + threadIdx.x];
        __syncthreads();
        #pragma unroll
        for (int t = TT - 1; t >= 0; --t) {
            // contribution at x = x0+t : Re(beta(x)) + Re(w2 * H(x+1))
            sbuf[n][t] = fmaf(w2r, Hr, fmaf(-w2i, Hi, br));
            float uu = su[t];
            float hr = fmaf(zr, Hr, fmaf(-zi, Hi, uu));   // H(x) = z H(x+1) + u[x]
            float hi = fmaf(zi, Hr, zr * Hi);
            Hr = hr; Hi = hi;
            float nbr = fmaf(zr, br, -zi * bi);           // beta(x-1) = z beta(x)
            float nbi = fmaf(zi, br,  zr * bi);
            br = nbr; bi = nbi;
        }
        __syncthreads();
        // reduce over the 64 states (two half-sums, then combine)
        float acc = 0.0f;
        #pragma unroll
        for (int k = 0; k < 32; ++k) acc += sbuf[nh * 32 + k][tred];
        pbuf[nh][tred] = acc;
        __syncthreads();
        if (threadIdx.x < TT) {
            int t = threadIdx.x;
            float yv = pbuf[0][t] + pbuf[1][t] + Dd * su[t];
            float gv = 0.5f * yv * (1.0f + erff(yv * 0.7071067811865475f));  // exact GELU
            gb[x0 + t] = gv;
        }
    }
}

// ---------------- kernel 4: SGEMM (W_out @ gelu_y) + GLU + mean fused -------
// C[1024,65536] = W[1024,512] @ YG[512,65536]; block computes 64 a-rows and
// their 64 g-partners, applies a*sigmoid(g), reduces its 128 columns, atomics
// into g_pooled[b, c].
#define BM 128
#define BN 128
#define BK 16
#define AS(buf,k,m) sh[(buf)*(BK*BM) + (k)*BM + (m)]
#define BS(buf,k,nn) sh[2*BK*BM + (buf)*(BK*BN) + (k)*BN + (nn)]

__global__ __launch_bounds__(256) void k_gemm(const float* __restrict__ W,
                                              const float* __restrict__ bout) {
    __shared__ __align__(16) float sh[2*BK*BM + 2*BK*BN + 64*16];
    float* red = sh + 2*BK*BM + 2*BK*BN;

    int rblk = blockIdx.x;               // 0..7  (64 a-channels each)
    int nblk = blockIdx.y;               // 0..511 (128 columns each)
    int tid  = threadIdx.x;
    int tx = tid & 15, ty = tid >> 4;
    int col0 = nblk * BN;
    int b    = col0 >> 12;               // column blocks never straddle a batch
    const float* yg = g_gelu + (size_t)b * DMODEL * LEN + (col0 & (LEN - 1));

    float acc[8][8];
    #pragma unroll
    for (int i = 0; i < 8; ++i)
        #pragma unroll
        for (int j = 0; j < 8; ++j) acc[i][j] = 0.0f;

    // prologue: tile 0 -> buffer 0
    #pragma unroll
    for (int i = 0; i < 2; ++i) {
        int lin = tid + i * 256;
        int r = lin >> 2, kq = (lin & 3) << 2;
        int wrow = (r < 64) ? (rblk * 64 + r) : (448 + rblk * 64 + r);
        float4 v = *reinterpret_cast<const float4*>(W + wrow * 512 + kq);
        AS(0, kq + 0, r) = v.x; AS(0, kq + 1, r) = v.y;
        AS(0, kq + 2, r) = v.z; AS(0, kq + 3, r) = v.w;
        int k = lin >> 5, nq = (lin & 31) << 2;
        float4 bv = *reinterpret_cast<const float4*>(yg + (size_t)k * LEN + nq);
        *reinterpret_cast<float4*>(&BS(0, k, nq)) = bv;
    }
    __syncthreads();

    for (int k0 = 0; k0 < 512; k0 += BK) {
        int buf = (k0 >> 4) & 1;
        bool hasn = (k0 + BK) < 512;
        float4 pa[2], pb[2];
        if (hasn) {
            #pragma unroll
            for (int i = 0; i < 2; ++i) {
                int lin = tid + i * 256;
                int r = lin >> 2, kq = (lin & 3) << 2;
                int wrow = (r < 64) ? (rblk * 64 + r) : (448 + rblk * 64 + r);
                pa[i] = *reinterpret_cast<const float4*>(W + wrow * 512 + (k0 + BK) + kq);
                int k = lin >> 5, nq = (lin & 31) << 2;
                pb[i] = *reinterpret_cast<const float4*>(yg + (size_t)(k0 + BK + k) * LEN + nq);
            }
        }
        #pragma unroll
        for (int kk = 0; kk < BK; ++kk) {
            float4 a0 = *reinterpret_cast<float4*>(&AS(buf, kk, ty * 8));
            float4 a1 = *reinterpret_cast<float4*>(&AS(buf, kk, ty * 8 + 4));
            float4 b0 = *reinterpret_cast<float4*>(&BS(buf, kk, tx * 8));
            float4 b1 = *reinterpret_cast<float4*>(&BS(buf, kk, tx * 8 + 4));
            float af[8] = {a0.x, a0.y, a0.z, a0.w, a1.x, a1.y, a1.z, a1.w};
            float bf[8] = {b0.x, b0.y, b0.z, b0.w, b1.x, b1.y, b1.z, b1.w};
            #pragma unroll
            for (int i = 0; i < 8; ++i)
                #pragma unroll
                for (int j = 0; j < 8; ++j)
                    acc[i][j] = fmaf(af[i], bf[j], acc[i][j]);
        }
        if (hasn) {
            int nb = buf ^ 1;
            #pragma unroll
            for (int i = 0; i < 2; ++i) {
                int lin = tid + i * 256;
                int r = lin >> 2, kq = (lin & 3) << 2;
                AS(nb, kq + 0, r) = pa[i].x; AS(nb, kq + 1, r) = pa[i].y;
                AS(nb, kq + 2, r) = pa[i].z; AS(nb, kq + 3, r) = pa[i].w;
                int k = lin >> 5, nq = (lin & 31) << 2;
                *reinterpret_cast<float4*>(&BS(nb, k, nq)) = pb[i];
            }
        }
        __syncthreads();
    }

    // epilogue: GLU + per-block column reduction (+ bias)
    float* Sg = sh;                        // [64][128] reuses As/Bs space
    if (ty >= 8) {                         // g rows: channel c, W row 512+c
        int rl = (ty - 8) * 8;
        #pragma unroll
        for (int i = 0; i < 8; ++i) {
            float bo = bout[512 + rblk * 64 + rl + i];
            #pragma unroll
            for (int j = 0; j < 8; ++j) {
                float gv = acc[i][j] + bo;
                Sg[(rl + i) * 128 + tx * 8 + j] = 1.0f / (1.0f + expf(-gv));
            }
        }
    }
    __syncthreads();
    if (ty < 8) {                          // a rows
        int rl = ty * 8;
        #pragma unroll
        for (int i = 0; i < 8; ++i) {
            float bo = bout[rblk * 64 + rl + i];
            float rs = 0.0f;
            #pragma unroll
            for (int j = 0; j < 8; ++j) {
                float av = acc[i][j] + bo;
                rs += av * Sg[(rl + i) * 128 + tx * 8 + j];
            }
            red[(rl + i) * 16 + tx] = rs;
        }
    }
    __syncthreads();
    if (tid < 64) {
        float s = 0.0f;
        #pragma unroll
        for (int k = 0; k < 16; ++k) s += red[tid * 16 + k];
        atomicAdd(&g_pooled[b * DMODEL + rblk * 64 + tid], s);
    }
}

// ---------------- kernel 5: mean scale + decoder ----------------------------
__global__ void k_final(const float* __restrict__ Wd,
                        const float* __restrict__ bd,
                        float* __restrict__ out) {
    int b = blockIdx.x;
    __shared__ float r[256];
    float s = 0.0f;
    for (int c = threadIdx.x; c < DMODEL; c += 256)
        s += Wd[c] * g_pooled[b * DMODEL + c];
    r[threadIdx.x] = s;
    __syncthreads();
    for (int st = 128; st > 0; st >>= 1) {
        if (threadIdx.x < st) r[threadIdx.x] += r[threadIdx.x + st];
        __syncthreads();
    }
    if (threadIdx.x == 0) out[b] = r[0] * (1.0f / (float)LEN) + bd[0];
}

// ---------------- launch -----------------------------------------------------
extern "C" void kernel_launch(void* const* d_in, const int* in_sizes, int n_in,
                              void* d_out, int out_size) {
    const float* u          = (const float*)d_in[0];
    const float* log_dt     = (const float*)d_in[1];
    const float* log_A_real = (const float*)d_in[2];
    const float* A_imag     = (const float*)d_in[3];
    const float* B_re       = (const float*)d_in[4];
    const float* B_im       = (const float*)d_in[5];
    const float* C_re       = (const float*)d_in[6];
    const float* C_im       = (const float*)d_in[7];
    const float* Dp         = (const float*)d_in[8];
    const float* W_out      = (const float*)d_in[9];
    const float* b_out      = (const float*)d_in[10];
    const float* W_dec      = (const float*)d_in[11];
    const float* b_dec      = (const float*)d_in[12];
    float* out = (float*)d_out;

    k_params<<<(DMODEL * DSTATE + 127) / 128, 128>>>(log_dt, log_A_real, A_imag,
                                                     B_re, B_im, C_re, C_im);
    k_zero<<<(BATCH * DMODEL + 255) / 256, 256>>>();
    k_scan<<<BATCH * DMODEL, 64>>>(u, Dp);
    dim3 gg(8, (BATCH * LEN) / BN);
    k_gemm<<<gg, 256>>>(W_out, b_out);
    k_final<<<BATCH, 256>>>(W_dec, b_dec, out);
}

// round 7
// speedup vs baseline: 1.7200x; 1.7200x over previous
#include <cuda_runtime.h>
#include <math.h>

#define BATCH   16
#define DMODEL  512
#define DSTATE  64
#define LEN     4096
#define TT      32

// ---------------- scratch (device globals: no allocations allowed) ----------
__device__ __align__(16) float g_zr[DMODEL*DSTATE];
__device__ __align__(16) float g_zi[DMODEL*DSTATE];
__device__ __align__(16) float g_wr[DMODEL*DSTATE];
__device__ __align__(16) float g_wi[DMODEL*DSTATE];
__device__ __align__(16) float g_w2r[DMODEL*DSTATE];
__device__ __align__(16) float g_w2i[DMODEL*DSTATE];
__device__ __align__(16) float g_gelu[(size_t)BATCH*DMODEL*LEN];   // 128 MB
__device__ __align__(16) float g_pooled[BATCH*DMODEL];
// W pre-packed into mma fragment order (tf32 bits): [rblk8][kt32][h2][mf8][lane32][reg4]
__device__ __align__(16) unsigned int g_Wp[8*32*2048];

__device__ __forceinline__ unsigned int f2tf32(float x) {
    unsigned int r;
    asm("cvt.rna.tf32.f32 %0, %1;" : "=r"(r) : "f"(x));
    return r;
}

// ---------------- kernel 1: SSM constants (fp64 for phase accuracy) ---------
__global__ void k_params(const float* __restrict__ log_dt,
                         const float* __restrict__ log_A_real,
                         const float* __restrict__ A_imag,
                         const float* __restrict__ B_re,
                         const float* __restrict__ B_im,
                         const float* __restrict__ C_re,
                         const float* __restrict__ C_im) {
    int i = blockIdx.x * blockDim.x + threadIdx.x;
    if (i >= DMODEL * DSTATE) return;
    int d = i / DSTATE;
    double dt   = exp((double)log_dt[d]);
    double Ar   = -exp((double)log_A_real[i]);
    double Ai   = (double)A_imag[i];
    double dtAr = Ar * dt, dtAi = Ai * dt;
    double er = exp(dtAr);
    double zr = er * cos(dtAi), zi = er * sin(dtAi);
    double den  = Ar * Ar + Ai * Ai;
    double numr = zr - 1.0, numi = zi;
    double qr = (numr * Ar + numi * Ai) / den;
    double qi = (numi * Ar - numr * Ai) / den;
    double Br = (double)B_re[i], Bi = (double)B_im[i];
    double bbr = qr * Br - qi * Bi, bbi = qr * Bi + qi * Br;
    double Cr = (double)C_re[i], Ci = (double)C_im[i];
    double wr = Cr * bbr - Ci * bbi, wi = Cr * bbi + Ci * bbr;
    double eL = exp((double)LEN * dtAr);
    double ph = (double)LEN * dtAi;
    double zLr = eL * cos(ph), zLi = eL * sin(ph);
    double w2r = -(wr * zLr - wi * zLi);
    double w2i = -(wr * zLi + wi * zLr);
    g_zr[i] = (float)zr;  g_zi[i] = (float)zi;
    g_wr[i] = (float)wr;  g_wi[i] = (float)wi;
    g_w2r[i] = (float)w2r; g_w2i[i] = (float)w2i;
}

// ---------------- kernel 1b: pack W into tf32 mma fragment order ------------
// element (rblk, kt, h, mf8, lane, reg):
//   m = mf8*16 + (lane>>2) + 8*(reg&1)   (block row 0..127)
//   k = kt*16 + h*8 + (lane&3) + 4*(reg>>1)
//   wrow = (m<64) ? rblk*64+m : 448+rblk*64+m
__global__ void k_packW(const float* __restrict__ W) {
    int flat = blockIdx.x * blockDim.x + threadIdx.x;   // 524288 total
    int reg  = flat & 3;
    int lane = (flat >> 2) & 31;
    int mf8  = (flat >> 7) & 7;
    int h    = (flat >> 10) & 1;
    int kt   = (flat >> 11) & 31;
    int rb   = flat >> 16;
    int m = mf8 * 16 + (lane >> 2) + 8 * (reg & 1);
    int k = kt * 16 + h * 8 + (lane & 3) + 4 * (reg >> 1);
    int wrow = (m < 64) ? rb * 64 + m : 448 + rb * 64 + m;
    g_Wp[flat] = f2tf32(W[wrow * 512 + k]);
}

// ---------------- kernel 2: zero pooled accumulator -------------------------
__global__ void k_zero() {
    int i = blockIdx.x * blockDim.x + threadIdx.x;
    if (i < BATCH * DMODEL) g_pooled[i] = 0.0f;
}

// ---------------- kernel 3: two-pass backward scan (E-form) + skip + GELU ---
// y[x] = Re(E(x)),  E(L-1) = w*H0,  E(x-1) = z*E(x) + w2*u[x]
__global__ __launch_bounds__(64) void k_scan(const float* __restrict__ u,
                                             const float* __restrict__ Dp) {
    __shared__ float su[TT];
    __shared__ float sbuf[DSTATE][TT + 1];
    __shared__ float pbuf[2][TT];

    int bd = blockIdx.x;                 // b*DMODEL + d
    int d  = bd & (DMODEL - 1);
    const float* ub = u + (size_t)bd * LEN;
    float* gb = g_gelu + (size_t)bd * LEN;

    int n  = threadIdx.x;
    int dn = d * DSTATE + n;
    float zr = g_zr[dn],  zi = g_zi[dn];
    float wr = g_wr[dn],  wi = g_wi[dn];
    float w2r = g_w2r[dn], w2i = g_w2i[dn];
    float Dd = Dp[d];

    // ---- pass A: H0 = sum_j u[j] z^j  (Horner from the top, stable) ----
    float Hr = 0.0f, Hi = 0.0f;
    for (int x0 = LEN - TT; x0 >= 0; x0 -= TT) {
        __syncthreads();
        if (threadIdx.x < TT) su[threadIdx.x] = ub[x0 + threadIdx.x];
        __syncthreads();
        #pragma unroll
        for (int t = TT - 1; t >= 0; --t) {
            float uu = su[t];
            float hr = fmaf(zr, Hr, fmaf(-zi, Hi, uu));
            float hi = fmaf(zi, Hr, zr * Hi);
            Hr = hr; Hi = hi;
        }
    }
    float Er = fmaf(wr, Hr, -wi * Hi);   // E(L-1) = w * H0
    float Ei = fmaf(wr, Hi,  wi * Hr);

    // ---- pass B: emit y backward via single E recurrence ----
    int tred = threadIdx.x & 31;
    int nh   = threadIdx.x >> 5;
    for (int x0 = LEN - TT; x0 >= 0; x0 -= TT) {
        __syncthreads();
        if (threadIdx.x < TT) su[threadIdx.x] = ub[x0 + threadIdx.x];
        __syncthreads();
        #pragma unroll
        for (int t = TT - 1; t >= 0; --t) {
            sbuf[n][t] = Er;                          // y contribution at x=x0+t
            float uu = su[t];
            float er = fmaf(zr, Er, fmaf(-zi, Ei, w2r * uu));
            float ei = fmaf(zi, Er, fmaf( zr, Ei, w2i * uu));
            Er = er; Ei = ei;
        }
        __syncthreads();
        float acc = 0.0f;
        #pragma unroll
        for (int k = 0; k < 32; ++k) acc += sbuf[nh * 32 + k][tred];
        pbuf[nh][tred] = acc;
        __syncthreads();
        if (threadIdx.x < TT) {
            int t = threadIdx.x;
            float yv = pbuf[0][t] + pbuf[1][t] + Dd * su[t];
            float gv = 0.5f * yv * (1.0f + erff(yv * 0.7071067811865475f));
            gb[x0 + t] = gv;
        }
    }
}

// ---------------- kernel 4: tf32 tensor-core GEMM + GLU + mean fused --------
// C[1024,65536] = W[1024,512] @ YG[512,65536], block tile 128x128,
// 8 warps (wm 0..1 over M, wn 0..3 over N), warp tile 64x32, mma m16n8k8 tf32.
#define SA_STRIDE 2048                 // floats per A buffer (2 k8 x 8 mf x 128)
#define SB_GRP    66                   // per-(h,nf) group stride (64 + pad 2)
#define SB_STRIDE (32*SB_GRP)          // 2112 floats per B buffer

__device__ __forceinline__ void mma_tf32(float* c, const uint4 a, const uint2 b) {
    asm volatile(
        "mma.sync.aligned.m16n8k8.row.col.f32.tf32.tf32.f32 "
        "{%0,%1,%2,%3}, {%4,%5,%6,%7}, {%8,%9}, {%0,%1,%2,%3};"
        : "+f"(c[0]), "+f"(c[1]), "+f"(c[2]), "+f"(c[3])
        : "r"(a.x), "r"(a.y), "r"(a.z), "r"(a.w), "r"(b.x), "r"(b.y));
}

__global__ __launch_bounds__(256) void k_gemm(const float* __restrict__ bout) {
    __shared__ __align__(16) float sh[8576];
    float* sA = sh;                       // 2 x 2048
    float* sB = sh + 2 * SA_STRIDE;       // 2 x 2112

    int tid = threadIdx.x;
    int w = tid >> 5, lane = tid & 31;
    int wm = w & 1, wn = w >> 1;
    int rblk = blockIdx.x;                // 0..7
    int nblk = blockIdx.y;                // 0..511
    int col0 = nblk * 128;
    int b = col0 >> 12;
    const float* yg = g_gelu + (size_t)b * DMODEL * LEN + (col0 & (LEN - 1));
    const unsigned int* Wp = g_Wp + rblk * (32 * 2048);

    float acc[4][4][4];
    #pragma unroll
    for (int i = 0; i < 4; ++i)
        #pragma unroll
        for (int j = 0; j < 4; ++j)
            #pragma unroll
            for (int r = 0; r < 4; ++r) acc[i][j][r] = 0.0f;

    // ---- prologue: pack ktile 0 into buffer 0 ----
    #pragma unroll
    for (int i = 0; i < 2; ++i) {
        int ia = tid + i * 256;
        uint4 va = *reinterpret_cast<const uint4*>(Wp + (size_t)ia * 4);
        *reinterpret_cast<uint4*>(reinterpret_cast<unsigned int*>(sA) + ia * 4) = va;
        int k = ia >> 5, n0 = (ia & 31) << 2;
        float4 vb = *reinterpret_cast<const float4*>(yg + (size_t)k * LEN + n0);
        float v[4] = {vb.x, vb.y, vb.z, vb.w};
        int h = k >> 3, kk = k & 3, reg = (k >> 2) & 1;
        #pragma unroll
        for (int e = 0; e < 4; ++e) {
            int nn = n0 + e;
            int l = ((nn & 7) << 2) | kk;
            sB[(h * 16 + (nn >> 3)) * SB_GRP + l * 2 + reg] = __uint_as_float(f2tf32(v[e]));
        }
    }
    __syncthreads();

    for (int kt = 0; kt < 32; ++kt) {
        int buf = kt & 1;
        bool has = kt < 31;
        uint4 pa[2]; float4 pb[2];
        if (has) {
            #pragma unroll
            for (int i = 0; i < 2; ++i) {
                int ia = tid + i * 256;
                pa[i] = *reinterpret_cast<const uint4*>(Wp + (size_t)(kt + 1) * 2048 + (size_t)ia * 4);
                int k = ia >> 5, n0 = (ia & 31) << 2;
                pb[i] = *reinterpret_cast<const float4*>(yg + (size_t)((kt + 1) * 16 + k) * LEN + n0);
            }
        }
        // ---- compute on buf ----
        const float* sAb = sA + buf * SA_STRIDE;
        const float* sBb = sB + buf * SB_STRIDE;
        #pragma unroll
        for (int h = 0; h < 2; ++h) {
            uint4 af[4]; uint2 bf[4];
            #pragma unroll
            for (int mf = 0; mf < 4; ++mf)
                af[mf] = *reinterpret_cast<const uint4*>(sAb + ((h * 8 + wm * 4 + mf) * 128 + lane * 4));
            #pragma unroll
            for (int nf = 0; nf < 4; ++nf)
                bf[nf] = *reinterpret_cast<const uint2*>(sBb + (h * 16 + wn * 4 + nf) * SB_GRP + lane * 2);
            #pragma unroll
            for (int mf = 0; mf < 4; ++mf)
                #pragma unroll
                for (int nf = 0; nf < 4; ++nf)
                    mma_tf32(acc[mf][nf], af[mf], bf[nf]);
        }
        // ---- store prefetched tile to buf^1 ----
        if (has) {
            int nb = buf ^ 1;
            #pragma unroll
            for (int i = 0; i < 2; ++i) {
                int ia = tid + i * 256;
                *reinterpret_cast<uint4*>(reinterpret_cast<unsigned int*>(sA + nb * SA_STRIDE) + ia * 4) = pa[i];
                int k = ia >> 5, n0 = (ia & 31) << 2;
                float v[4] = {pb[i].x, pb[i].y, pb[i].z, pb[i].w};
                int h = k >> 3, kk = k & 3, reg = (k >> 2) & 1;
                float* sBn = sB + nb * SB_STRIDE;
                #pragma unroll
                for (int e = 0; e < 4; ++e) {
                    int nn = n0 + e;
                    int l = ((nn & 7) << 2) | kk;
                    sBn[(h * 16 + (nn >> 3)) * SB_GRP + l * 2 + reg] = __uint_as_float(f2tf32(v[e]));
                }
            }
        }
        __syncthreads();
    }

    // ---- epilogue: GLU + per-block column reduction ----
    float* Sg  = sh;                      // [64][129]
    float* red = sh + 64 * 129;           // [64][4]

    if (wm == 1) {                        // g rows (block rows 64..127)
        #pragma unroll
        for (int mf = 0; mf < 4; ++mf)
            #pragma unroll
            for (int hi = 0; hi < 2; ++hi) {
                int row = mf * 16 + (lane >> 2) + 8 * hi;       // g channel (0..63)
                float bo = bout[512 + rblk * 64 + row];
                #pragma unroll
                for (int nf = 0; nf < 4; ++nf)
                    #pragma unroll
                    for (int c01 = 0; c01 < 2; ++c01) {
                        int col = wn * 32 + nf * 8 + ((lane & 3) << 1) + c01;
                        float gv = acc[mf][nf][2 * hi + c01] + bo;
                        Sg[row * 129 + col] = 1.0f / (1.0f + expf(-gv));
                    }
            }
    }
    __syncthreads();
    if (wm == 0) {                        // a rows
        #pragma unroll
        for (int mf = 0; mf < 4; ++mf)
            #pragma unroll
            for (int hi = 0; hi < 2; ++hi) {
                int row = mf * 16 + (lane >> 2) + 8 * hi;
                float bo = bout[rblk * 64 + row];
                float rs = 0.0f;
                #pragma unroll
                for (int nf = 0; nf < 4; ++nf)
                    #pragma unroll
                    for (int c01 = 0; c01 < 2; ++c01) {
                        int col = wn * 32 + nf * 8 + ((lane & 3) << 1) + c01;
                        rs += (acc[mf][nf][2 * hi + c01] + bo) * Sg[row * 129 + col];
                    }
                rs += __shfl_xor_sync(0xffffffffu, rs, 1);
                rs += __shfl_xor_sync(0xffffffffu, rs, 2);
                if ((lane & 3) == 0) red[row * 4 + wn] = rs;
            }
    }
    __syncthreads();
    if (tid < 64) {
        float s = red[tid * 4] + red[tid * 4 + 1] + red[tid * 4 + 2] + red[tid * 4 + 3];
        atomicAdd(&g_pooled[b * DMODEL + rblk * 64 + tid], s);
    }
}

// ---------------- kernel 5: mean scale + decoder ----------------------------
__global__ void k_final(const float* __restrict__ Wd,
                        const float* __restrict__ bd,
                        float* __restrict__ out) {
    int b = blockIdx.x;
    __shared__ float r[256];
    float s = 0.0f;
    for (int c = threadIdx.x; c < DMODEL; c += 256)
        s += Wd[c] * g_pooled[b * DMODEL + c];
    r[threadIdx.x] = s;
    __syncthreads();
    for (int st = 128; st > 0; st >>= 1) {
        if (threadIdx.x < st) r[threadIdx.x] += r[threadIdx.x + st];
        __syncthreads();
    }
    if (threadIdx.x == 0) out[b] = r[0] * (1.0f / (float)LEN) + bd[0];
}

// ---------------- launch -----------------------------------------------------
extern "C" void kernel_launch(void* const* d_in, const int* in_sizes, int n_in,
                              void* d_out, int out_size) {
    const float* u          = (const float*)d_in[0];
    const float* log_dt     = (const float*)d_in[1];
    const float* log_A_real = (const float*)d_in[2];
    const float* A_imag     = (const float*)d_in[3];
    const float* B_re       = (const float*)d_in[4];
    const float* B_im       = (const float*)d_in[5];
    const float* C_re       = (const float*)d_in[6];
    const float* C_im       = (const float*)d_in[7];
    const float* Dp         = (const float*)d_in[8];
    const float* W_out      = (const float*)d_in[9];
    const float* b_out      = (const float*)d_in[10];
    const float* W_dec      = (const float*)d_in[11];
    const float* b_dec      = (const float*)d_in[12];
    float* out = (float*)d_out;

    k_params<<<(DMODEL * DSTATE + 127) / 128, 128>>>(log_dt, log_A_real, A_imag,
                                                     B_re, B_im, C_re, C_im);
    k_packW<<<(8 * 32 * 2048) / 256, 256>>>(W_out);
    k_zero<<<(BATCH * DMODEL + 255) / 256, 256>>>();
    k_scan<<<BATCH * DMODEL, 64>>>(u, Dp);
    dim3 gg(8, (BATCH * LEN) / 128);
    k_gemm<<<gg, 256>>>(b_out);
    k_final<<<BATCH, 256>>>(W_dec, b_dec, out);
}